// round 14
// baseline (speedup 1.0000x reference)
#include <cuda_runtime.h>
#include <cuda_fp16.h>
#include <math.h>
#include <stdint.h>

// ---------------------------------------------------------------------------
// Problem constants
// ---------------------------------------------------------------------------
#define B_ 2
#define NV 4
#define H_ 240
#define W_ 240
#define H1_ 120
#define W1_ 120
#define D_ 32
#define NPB 131072
#define PT (B_ * NPB)
#define INBASE 70
#define XPAD_H 80             // padded fp16 feature row (160 B)
#define DH 128
#define TM 192                // points per tile (12 warps x 16 rows)
#define NT ((PT + TM - 1) / TM)   // 1366 tiles (last partial: 64 valid rows)
#define FF_GRID 148
#define FF_THREADS 384        // 12 warps -> reg cap 170/thread (no spills)

#define WS_W 136              // halves per weight row [n][k] (272 B, conflict-free)
#define WS_W32 68
#define WL_W32 (128 * WS_W32)
#define WS_ALL_BYTES (5 * 128 * WS_W * 2)  // 174080

#define ACTIN_W32 44          // words per act-in row (176 B; bank = 12r+cp, conflict-free)
#define ACTIN_BYTES (TM * ACTIN_W32 * 4)   // 33792

// ---------------------------------------------------------------------------
// Scratch (device globals). g_xh padded by one tile so the partial last tile's
// staging reads stay in-bounds (device globals are zero-initialized).
// ---------------------------------------------------------------------------
__device__ __half g_xh[((size_t)PT + TM) * XPAD_H];
__device__ __half g_featsTh[(size_t)B_ * NV * H1_ * W1_ * D_];
__device__ __half g_imgsTh[(size_t)B_ * NV * H_ * W_ * 3];
__device__ float  g_proj[B_ * NV * 12];
__device__ __half g_wpadh[5 * 128 * WS_W];

// ---------------------------------------------------------------------------
// helpers
// ---------------------------------------------------------------------------
__device__ __forceinline__ void mma_f16(float (&d)[4], const uint32_t (&a)[4],
                                        const uint32_t (&b)[2]) {
    asm volatile(
        "mma.sync.aligned.m16n8k16.row.col.f32.f16.f16.f32 "
        "{%0,%1,%2,%3}, {%4,%5,%6,%7}, {%8,%9}, {%0,%1,%2,%3};"
        : "+f"(d[0]), "+f"(d[1]), "+f"(d[2]), "+f"(d[3])
        : "r"(a[0]), "r"(a[1]), "r"(a[2]), "r"(a[3]), "r"(b[0]), "r"(b[1]));
}

__device__ __forceinline__ uint32_t smem_u32(const void* p) {
    return (uint32_t)__cvta_generic_to_shared(p);
}

__device__ __forceinline__ void cp16(uint32_t saddr, const void* g) {
    asm volatile("cp.async.cg.shared.global [%0], [%1], 16;" :: "r"(saddr), "l"(g));
}
#define CP_COMMIT() asm volatile("cp.async.commit_group;")
#define CP_WAIT0()  asm volatile("cp.async.wait_group 0;")

__device__ __forceinline__ uint32_t pack_h2(float x, float y) {
    __half2 h = __halves2half2(__float2half_rn(x), __float2half_rn(y));
    return *reinterpret_cast<uint32_t*>(&h);
}

__device__ __forceinline__ void h8_to_f(const uint4& u, float* f) {
    const __half2* h = reinterpret_cast<const __half2*>(&u);
#pragma unroll
    for (int i = 0; i < 4; i++) {
        float2 v = __half22float2(h[i]);
        f[i * 2 + 0] = v.x;
        f[i * 2 + 1] = v.y;
    }
}

// ---------------------------------------------------------------------------
// Kernel 0: projection matrices  P = K @ inv(c2w)[0:3, :]
// ---------------------------------------------------------------------------
__global__ void proj_kernel(const float* __restrict__ cams) {
    int i = threadIdx.x;
    if (i >= B_ * NV) return;
    const float* c = cams + i * 27;
    float K[9];
#pragma unroll
    for (int j = 0; j < 9; j++) K[j] = c[2 + j];
    float m[16];
#pragma unroll
    for (int j = 0; j < 16; j++) m[j] = c[11 + j];

    float inv[16];
    inv[0]  =  m[5]*m[10]*m[15] - m[5]*m[11]*m[14] - m[9]*m[6]*m[15] + m[9]*m[7]*m[14] + m[13]*m[6]*m[11] - m[13]*m[7]*m[10];
    inv[4]  = -m[4]*m[10]*m[15] + m[4]*m[11]*m[14] + m[8]*m[6]*m[15] - m[8]*m[7]*m[14] - m[12]*m[6]*m[11] + m[12]*m[7]*m[10];
    inv[8]  =  m[4]*m[9]*m[15]  - m[4]*m[11]*m[13] - m[8]*m[5]*m[15] + m[8]*m[7]*m[13] + m[12]*m[5]*m[11] - m[12]*m[7]*m[9];
    inv[12] = -m[4]*m[9]*m[14]  + m[4]*m[10]*m[13] + m[8]*m[5]*m[14] - m[8]*m[6]*m[13] - m[12]*m[5]*m[10] + m[12]*m[6]*m[9];
    inv[1]  = -m[1]*m[10]*m[15] + m[1]*m[11]*m[14] + m[9]*m[2]*m[15] - m[9]*m[3]*m[14] - m[13]*m[2]*m[11] + m[13]*m[3]*m[10];
    inv[5]  =  m[0]*m[10]*m[15] - m[0]*m[11]*m[14] - m[8]*m[2]*m[15] + m[8]*m[3]*m[14] + m[12]*m[2]*m[11] - m[12]*m[3]*m[10];
    inv[9]  = -m[0]*m[9]*m[15]  + m[0]*m[11]*m[13] + m[8]*m[1]*m[15] - m[8]*m[3]*m[13] - m[12]*m[1]*m[11] + m[12]*m[3]*m[9];
    inv[13] =  m[0]*m[9]*m[14]  - m[0]*m[10]*m[13] - m[8]*m[1]*m[14] + m[8]*m[2]*m[13] + m[12]*m[1]*m[10] - m[12]*m[2]*m[9];
    inv[2]  =  m[1]*m[6]*m[15]  - m[1]*m[7]*m[14]  - m[5]*m[2]*m[15] + m[5]*m[3]*m[14] + m[13]*m[2]*m[7]  - m[13]*m[3]*m[6];
    inv[6]  = -m[0]*m[6]*m[15]  + m[0]*m[7]*m[14]  + m[4]*m[2]*m[15] - m[4]*m[3]*m[14] - m[12]*m[2]*m[7]  + m[12]*m[3]*m[6];
    inv[10] =  m[0]*m[5]*m[15]  - m[0]*m[7]*m[13]  - m[4]*m[1]*m[15] + m[4]*m[3]*m[13] + m[12]*m[1]*m[7]  - m[12]*m[3]*m[5];
    inv[14] = -m[0]*m[5]*m[14]  + m[0]*m[6]*m[13]  + m[4]*m[1]*m[14] - m[4]*m[2]*m[13] - m[12]*m[1]*m[6]  + m[12]*m[2]*m[5];
    inv[3]  = -m[1]*m[6]*m[11]  + m[1]*m[7]*m[10]  + m[5]*m[2]*m[11] - m[5]*m[3]*m[10] - m[9]*m[2]*m[7]   + m[9]*m[3]*m[6];
    inv[7]  =  m[0]*m[6]*m[11]  - m[0]*m[7]*m[10]  - m[4]*m[2]*m[11] + m[4]*m[3]*m[10] + m[8]*m[2]*m[7]   - m[8]*m[3]*m[6];
    inv[11] = -m[0]*m[5]*m[11]  + m[0]*m[7]*m[9]   + m[4]*m[1]*m[11] - m[4]*m[3]*m[9]  - m[8]*m[1]*m[7]   + m[8]*m[3]*m[5];
    inv[15] =  m[0]*m[5]*m[10]  - m[0]*m[6]*m[9]   - m[4]*m[1]*m[10] + m[4]*m[2]*m[9]  + m[8]*m[1]*m[6]   - m[8]*m[2]*m[5];

    float det = m[0]*inv[0] + m[1]*inv[4] + m[2]*inv[8] + m[3]*inv[12];
    float id = 1.0f / det;
#pragma unroll
    for (int j = 0; j < 16; j++) inv[j] *= id;

#pragma unroll
    for (int r = 0; r < 3; r++) {
#pragma unroll
        for (int cc = 0; cc < 4; cc++) {
            float s = K[r*3+0]*inv[0*4+cc] + K[r*3+1]*inv[1*4+cc] + K[r*3+2]*inv[2*4+cc];
            g_proj[i*12 + r*4 + cc] = s;
        }
    }
}

// ---------------------------------------------------------------------------
// Weight prep: fp16, transposed [l][n][k]
// ---------------------------------------------------------------------------
__global__ void wprep_kernel(const float* __restrict__ w0, const float* __restrict__ w1,
                             const float* __restrict__ w2, const float* __restrict__ w3,
                             const float* __restrict__ w4) {
    int o = blockIdx.x * blockDim.x + threadIdx.x;
    if (o >= 5 * 128 * WS_W) return;
    int l = o / (128 * WS_W);
    int rem = o - l * 128 * WS_W;
    int n = rem / WS_W;
    int k = rem - n * WS_W;
    float v = 0.f;
    if (l == 0) {
        if (k < INBASE) v = w0[k * DH + n];
    } else if (k < DH) {
        const float* w = (l == 1) ? w1 : (l == 2) ? w2 : (l == 3) ? w3 : w4;
        v = w[k * DH + n];
    }
    g_wpadh[o] = __float2half_rn(v);
}

// ---------------------------------------------------------------------------
// Transposes to channel-last fp16
// ---------------------------------------------------------------------------
__global__ void tfeat_kernel(const float* __restrict__ f) {
    int o = blockIdx.x * blockDim.x + threadIdx.x;
    if (o >= B_ * NV * H1_ * W1_ * D_) return;
    int c = o & (D_ - 1);
    int rest = o >> 5;
    int x = rest % W1_;
    int t2 = rest / W1_;
    int y = t2 % H1_;
    int bv = t2 / H1_;
    g_featsTh[o] = __float2half_rn(f[((size_t)(bv * D_ + c)) * (H1_ * W1_) + y * W1_ + x]);
}

__global__ void timg_kernel(const float* __restrict__ im) {
    int o = blockIdx.x * blockDim.x + threadIdx.x;
    if (o >= B_ * NV * H_ * W_ * 3) return;
    int c = o % 3;
    int rest = o / 3;
    int x = rest % W_;
    int t2 = rest / W_;
    int y = t2 % H_;
    int bv = t2 / H_;
    g_imgsTh[o] = __float2half_rn(im[((size_t)(bv * 3 + c)) * (H_ * W_) + y * W_ + x]);
}

// ---------------------------------------------------------------------------
// Kernel 1: quad featurize (4 threads/point), fp16 taps -> g_xh [PT][80]
// ---------------------------------------------------------------------------
__global__ void __launch_bounds__(256) featurize_kernel(const float* __restrict__ xyz) {
    int t = blockIdx.x * blockDim.x + threadIdx.x;
    int gp = t >> 2;
    int q  = t & 3;
    if (gp >= PT) return;
    int b = gp / NPB;

    float X = xyz[(size_t)gp * 3 + 0];
    float Y = xyz[(size_t)gp * 3 + 1];
    float Z = xyz[(size_t)gp * 3 + 2];

    float fs[8], fq[8];
#pragma unroll
    for (int i = 0; i < 8; i++) { fs[i] = 0.f; fq[i] = 0.f; }
    float rs = 0.f, rq = 0.f;
    float s = 0.f;

    const float SX = (float)(W1_ - 1) / (float)(W_ - 1);
    const float SY = (float)(H1_ - 1) / (float)(H_ - 1);

#pragma unroll
    for (int v = 0; v < NV; v++) {
        const float* Pm = &g_proj[(b * NV + v) * 12];
        float pxn = Pm[0]*X + Pm[1]*Y + Pm[2]*Z  + Pm[3];
        float pyn = Pm[4]*X + Pm[5]*Y + Pm[6]*Z  + Pm[7];
        float pz  = Pm[8]*X + Pm[9]*Y + Pm[10]*Z + Pm[11];
        float d = fmaxf(pz, 1e-8f);
        float px = pxn / d;
        float py = pyn / d;
        bool inb = (pz > 1e-4f) && (px >= 0.f) && (px <= (float)(W_ - 1))
                                && (py >= 0.f) && (py <= (float)(H_ - 1));
        if (!inb) continue;
        s += 1.f;

        if (q < 3) {
            float x0f = floorf(px), y0f = floorf(py);
            float wx = px - x0f, wy = py - y0f;
            int x0 = (int)x0f;
            int y0 = (int)y0f;
            int x1 = min(x0 + 1, W_ - 1);
            int y1 = min(y0 + 1, H_ - 1);
            float w00 = (1.f - wx) * (1.f - wy);
            float w01 = wx * (1.f - wy);
            float w10 = (1.f - wx) * wy;
            float w11 = wx * wy;
            const __half* ib = g_imgsTh + (size_t)(b * NV + v) * H_ * W_ * 3 + q;
            float val = __half2float(ib[(size_t)(y0 * W_ + x0) * 3]) * w00
                      + __half2float(ib[(size_t)(y0 * W_ + x1) * 3]) * w01
                      + __half2float(ib[(size_t)(y1 * W_ + x0) * 3]) * w10
                      + __half2float(ib[(size_t)(y1 * W_ + x1) * 3]) * w11;
            rs += val;
            rq += val * val;
        }

        {
            float fx = px * SX;
            float fy = py * SY;
            float x0f = floorf(fx), y0f = floorf(fy);
            float wx = fx - x0f, wy = fy - y0f;
            int x0 = (int)x0f;
            int y0 = (int)y0f;
            int x1 = min(x0 + 1, W1_ - 1);
            int y1 = min(y0 + 1, H1_ - 1);
            float w00 = (1.f - wx) * (1.f - wy);
            float w01 = wx * (1.f - wy);
            float w10 = (1.f - wx) * wy;
            float w11 = wx * wy;
            const __half* fb = g_featsTh + (size_t)(b * NV + v) * H1_ * W1_ * D_ + q * 8;
            uint4 u00 = *reinterpret_cast<const uint4*>(fb + (size_t)(y0 * W1_ + x0) * D_);
            uint4 u01 = *reinterpret_cast<const uint4*>(fb + (size_t)(y0 * W1_ + x1) * D_);
            uint4 u10 = *reinterpret_cast<const uint4*>(fb + (size_t)(y1 * W1_ + x0) * D_);
            uint4 u11 = *reinterpret_cast<const uint4*>(fb + (size_t)(y1 * W1_ + x1) * D_);
            float a[8], bb[8], cc[8], dd[8];
            h8_to_f(u00, a); h8_to_f(u01, bb); h8_to_f(u10, cc); h8_to_f(u11, dd);
#pragma unroll
            for (int j = 0; j < 8; j++) {
                float vv = a[j]*w00 + bb[j]*w01 + cc[j]*w10 + dd[j]*w11;
                fs[j] += vv;
                fq[j] += vv * vv;
            }
        }
    }

    float denom = s + 1e-6f;
    float invd = 1.f / denom;
    float alpha = s * invd;
    float two_m_a = 2.f - alpha;
    __half* xo = g_xh + (size_t)gp * XPAD_H;

    if (q < 3) {
        float m  = rs * invd;
        float e2 = rq * invd;
        xo[q]      = __float2half_rn(m);
        xo[35 + q] = __float2half_rn(e2 - two_m_a * m * m);
    }
#pragma unroll
    for (int j = 0; j < 8; j++) {
        int i = 3 + q * 8 + j;
        float m  = fs[j] * invd;
        float e2 = fq[j] * invd;
        xo[i]      = __float2half_rn(m);
        xo[35 + i] = __float2half_rn(e2 - two_m_a * m * m);
    }
    if (q == 0) {
#pragma unroll
        for (int j = 70; j < XPAD_H; j++) xo[j] = __float2half_rn(0.f);
    }
}

// ---------------------------------------------------------------------------
// Kernel 2: fully-fused register-resident MLP. Persistent, 148 blocks x 384
// threads (12 warps = 3/SMSP; reg cap 170 -> no spills). Tile = 192 points.
// Last tile partial (64 valid); output stores guarded, staging reads padded.
// ---------------------------------------------------------------------------
__global__ void __launch_bounds__(FF_THREADS, 1) mlp_ff_kernel(
    const float* __restrict__ b0, const float* __restrict__ b1,
    const float* __restrict__ b2, const float* __restrict__ b3,
    const float* __restrict__ b4,
    const float* __restrict__ w5, const float* __restrict__ b5,
    const float* __restrict__ dw, const float* __restrict__ db,
    float* __restrict__ out) {

    extern __shared__ char smem[];
    uint32_t* actin = reinterpret_cast<uint32_t*>(smem);                 // ACTIN_BYTES
    uint32_t* wsm   = reinterpret_cast<uint32_t*>(smem + ACTIN_BYTES);   // WS_ALL_BYTES
    float* bias = reinterpret_cast<float*>(smem + ACTIN_BYTES + WS_ALL_BYTES);
    float* w5s  = bias + 5 * DH;
    float* dws  = w5s + DH * 3;

    const int tid  = threadIdx.x;
    const int lane = tid & 31;
    const int warp = tid >> 5;
    const int r  = lane >> 2;
    const int cp = lane & 3;
    const int R0 = warp * 16 + r;
    const int R1 = R0 + 8;

    const uint32_t s_act = smem_u32(actin);
    const uint32_t s_w   = smem_u32(wsm);

    // stage all 5 weight layers + first act tile
    for (int i = tid; i < WS_ALL_BYTES / 16; i += FF_THREADS)
        cp16(s_w + (uint32_t)i * 16, g_wpadh + i * 8);
    int tile = blockIdx.x;
    {
        const __half* gx = g_xh + (size_t)tile * TM * XPAD_H;
        for (int i = tid; i < TM * 10; i += FF_THREADS) {
            int row = i / 10, ch = i - row * 10;
            cp16(s_act + (uint32_t)(row * (ACTIN_W32 * 4) + ch * 16),
                 gx + (size_t)row * XPAD_H + ch * 8);
        }
    }
    CP_COMMIT();

    if (tid < DH) {
        bias[0 * DH + tid] = b0[tid];
        bias[1 * DH + tid] = b1[tid];
        bias[2 * DH + tid] = b2[tid];
        bias[3 * DH + tid] = b3[tid];
        bias[4 * DH + tid] = b4[tid];
        dws[tid] = dw[tid];
    }
    for (int i = tid; i < DH * 3; i += FF_THREADS) w5s[i] = w5[i];
    const float db0 = db[0];
    const float b50 = b5[0], b51 = b5[1], b52 = b5[2];

    float acc[16][4];
    uint32_t h[32];

    for (; tile < NT; tile += FF_GRID) {
        CP_WAIT0();
        __syncthreads();

        // ---- layer 0: A from actin (K=80 -> 5 ksteps) ----
#pragma unroll
        for (int j = 0; j < 16; j++)
#pragma unroll
            for (int d = 0; d < 4; d++) acc[j][d] = 0.f;
#pragma unroll
        for (int kt = 0; kt < 5; kt++) {
            uint32_t a[4];
            a[0] = actin[R0 * ACTIN_W32 + kt * 8 + cp];
            a[1] = actin[R1 * ACTIN_W32 + kt * 8 + cp];
            a[2] = actin[R0 * ACTIN_W32 + kt * 8 + 4 + cp];
            a[3] = actin[R1 * ACTIN_W32 + kt * 8 + 4 + cp];
#pragma unroll
            for (int j = 0; j < 16; j++) {
                uint32_t bfr[2];
                int bi = (j * 8 + r) * WS_W32 + kt * 8 + cp;
                bfr[0] = wsm[bi];
                bfr[1] = wsm[bi + 4];
                mma_f16(acc[j], a, bfr);
            }
        }

        // pf: bias, sigma head partials, convert to h
        {
            float sp0 = 0.f, sp1 = 0.f;
#pragma unroll
            for (int j = 0; j < 16; j++) {
                int c0 = j * 8 + cp * 2;
                float bv0 = bias[c0], bv1 = bias[c0 + 1];
                float v0 = acc[j][0] + bv0, v1 = acc[j][1] + bv1;
                float v2 = acc[j][2] + bv0, v3 = acc[j][3] + bv1;
                float d0 = dws[c0], d1 = dws[c0 + 1];
                sp0 = fmaf(v0, d0, fmaf(v1, d1, sp0));
                sp1 = fmaf(v2, d0, fmaf(v3, d1, sp1));
                h[j]      = pack_h2(v0, v1);
                h[16 + j] = pack_h2(v2, v3);
            }
            sp0 += __shfl_xor_sync(0xffffffff, sp0, 1);
            sp0 += __shfl_xor_sync(0xffffffff, sp0, 2);
            sp1 += __shfl_xor_sync(0xffffffff, sp1, 1);
            sp1 += __shfl_xor_sync(0xffffffff, sp1, 2);
            if (cp == 0) {
                size_t p = (size_t)tile * TM;
                if (p + R0 < PT) out[(p + R0) * 4 + 3] = fmaxf(sp0 + db0, 0.f);
                if (p + R1 < PT) out[(p + R1) * 4 + 3] = fmaxf(sp1 + db0, 0.f);
            }
        }

        __syncthreads();   // all warps done reading actin
        {
            int nt2 = tile + FF_GRID;
            if (nt2 < NT) {
                const __half* gx = g_xh + (size_t)nt2 * TM * XPAD_H;
                for (int i = tid; i < TM * 10; i += FF_THREADS) {
                    int row = i / 10, ch = i - row * 10;
                    cp16(s_act + (uint32_t)(row * (ACTIN_W32 * 4) + ch * 16),
                         gx + (size_t)row * XPAD_H + ch * 8);
                }
            }
        }
        CP_COMMIT();

        // ---- layers 1..4 ----
#pragma unroll 1
        for (int l = 1; l < 5; l++) {
            const uint32_t* wp = wsm + l * WL_W32;
            const float* bl = bias + l * DH;
#pragma unroll
            for (int j = 0; j < 16; j++)
#pragma unroll
                for (int d = 0; d < 4; d++) acc[j][d] = 0.f;
#pragma unroll
            for (int kt = 0; kt < 8; kt++) {
                uint32_t a[4];
                a[0] = h[2 * kt];
                a[1] = h[16 + 2 * kt];
                a[2] = h[2 * kt + 1];
                a[3] = h[16 + 2 * kt + 1];
#pragma unroll
                for (int j = 0; j < 16; j++) {
                    uint32_t bfr[2];
                    int bi = (j * 8 + r) * WS_W32 + kt * 8 + cp;
                    bfr[0] = wp[bi];
                    bfr[1] = wp[bi + 4];
                    mma_f16(acc[j], a, bfr);
                }
            }
            if (l < 4) {
#pragma unroll
                for (int j = 0; j < 16; j++) {
                    int c0 = j * 8 + cp * 2;
                    float bv0 = bl[c0], bv1 = bl[c0 + 1];
                    float v0 = acc[j][0] + bv0, v1 = acc[j][1] + bv1;
                    float v2 = acc[j][2] + bv0, v3 = acc[j][3] + bv1;
                    v0 = v0 > 0.f ? v0 : 0.01f * v0;
                    v1 = v1 > 0.f ? v1 : 0.01f * v1;
                    v2 = v2 > 0.f ? v2 : 0.01f * v2;
                    v3 = v3 > 0.f ? v3 : 0.01f * v3;
                    h[j]      = pack_h2(v0, v1);
                    h[16 + j] = pack_h2(v2, v3);
                }
            } else {
                float ra0 = 0.f, ra1 = 0.f, ra2 = 0.f;
                float rb0 = 0.f, rb1 = 0.f, rb2 = 0.f;
#pragma unroll
                for (int j = 0; j < 16; j++) {
                    int c0 = j * 8 + cp * 2;
                    float bv0 = bl[c0], bv1 = bl[c0 + 1];
                    float v0 = acc[j][0] + bv0, v1 = acc[j][1] + bv1;
                    float v2 = acc[j][2] + bv0, v3 = acc[j][3] + bv1;
                    v0 = v0 > 0.f ? v0 : 0.01f * v0;
                    v1 = v1 > 0.f ? v1 : 0.01f * v1;
                    v2 = v2 > 0.f ? v2 : 0.01f * v2;
                    v3 = v3 > 0.f ? v3 : 0.01f * v3;
                    float w00 = w5s[c0 * 3 + 0], w01 = w5s[c0 * 3 + 1], w02 = w5s[c0 * 3 + 2];
                    float w10 = w5s[(c0 + 1) * 3 + 0], w11 = w5s[(c0 + 1) * 3 + 1], w12 = w5s[(c0 + 1) * 3 + 2];
                    ra0 = fmaf(v0, w00, fmaf(v1, w10, ra0));
                    ra1 = fmaf(v0, w01, fmaf(v1, w11, ra1));
                    ra2 = fmaf(v0, w02, fmaf(v1, w12, ra2));
                    rb0 = fmaf(v2, w00, fmaf(v3, w10, rb0));
                    rb1 = fmaf(v2, w01, fmaf(v3, w11, rb1));
                    rb2 = fmaf(v2, w02, fmaf(v3, w12, rb2));
                }
                ra0 += __shfl_xor_sync(0xffffffff, ra0, 1);
                ra0 += __shfl_xor_sync(0xffffffff, ra0, 2);
                ra1 += __shfl_xor_sync(0xffffffff, ra1, 1);
                ra1 += __shfl_xor_sync(0xffffffff, ra1, 2);
                ra2 += __shfl_xor_sync(0xffffffff, ra2, 1);
                ra2 += __shfl_xor_sync(0xffffffff, ra2, 2);
                rb0 += __shfl_xor_sync(0xffffffff, rb0, 1);
                rb0 += __shfl_xor_sync(0xffffffff, rb0, 2);
                rb1 += __shfl_xor_sync(0xffffffff, rb1, 1);
                rb1 += __shfl_xor_sync(0xffffffff, rb1, 2);
                rb2 += __shfl_xor_sync(0xffffffff, rb2, 1);
                rb2 += __shfl_xor_sync(0xffffffff, rb2, 2);
                if (cp == 0) {
                    size_t p = (size_t)tile * TM;
                    if (p + R0 < PT) {
                        size_t o0 = (p + R0) * 4;
                        out[o0 + 0] = tanhf(ra0 + b50);
                        out[o0 + 1] = tanhf(ra1 + b51);
                        out[o0 + 2] = tanhf(ra2 + b52);
                    }
                    if (p + R1 < PT) {
                        size_t o1 = (p + R1) * 4;
                        out[o1 + 0] = tanhf(rb0 + b50);
                        out[o1 + 1] = tanhf(rb1 + b51);
                        out[o1 + 2] = tanhf(rb2 + b52);
                    }
                }
            }
        }
    }
}

// ---------------------------------------------------------------------------
// Launch
// ---------------------------------------------------------------------------
extern "C" void kernel_launch(void* const* d_in, const int* in_sizes, int n_in,
                              void* d_out, int out_size) {
    const float* xyz       = (const float*)d_in[0];
    const float* src_imgs  = (const float*)d_in[2];
    const float* src_cams  = (const float*)d_in[3];
    const float* src_feats = (const float*)d_in[4];
    const float* w0 = (const float*)d_in[5];
    const float* b0 = (const float*)d_in[6];
    const float* w1 = (const float*)d_in[7];
    const float* b1 = (const float*)d_in[8];
    const float* w2 = (const float*)d_in[9];
    const float* b2 = (const float*)d_in[10];
    const float* w3 = (const float*)d_in[11];
    const float* b3 = (const float*)d_in[12];
    const float* w4 = (const float*)d_in[13];
    const float* b4 = (const float*)d_in[14];
    const float* w5 = (const float*)d_in[15];
    const float* b5 = (const float*)d_in[16];
    const float* dw = (const float*)d_in[17];
    const float* db = (const float*)d_in[18];
    float* out = (float*)d_out;

    const int smem_bytes = ACTIN_BYTES + WS_ALL_BYTES
                         + (5 * DH + DH * 3 + DH) * (int)sizeof(float);
    cudaFuncSetAttribute(mlp_ff_kernel,
                         cudaFuncAttributeMaxDynamicSharedMemorySize, smem_bytes);

    proj_kernel<<<1, 32>>>(src_cams);
    wprep_kernel<<<(5 * 128 * WS_W + 255) / 256, 256>>>(w0, w1, w2, w3, w4);
    tfeat_kernel<<<(B_ * NV * H1_ * W1_ * D_) / 256, 256>>>(src_feats);
    timg_kernel<<<(B_ * NV * H_ * W_ * 3 + 255) / 256, 256>>>(src_imgs);
    featurize_kernel<<<(PT * 4) / 256, 256>>>(xyz);
    mlp_ff_kernel<<<FF_GRID, FF_THREADS, smem_bytes>>>(b0, b1, b2, b3, b4,
                                                       w5, b5, dw, db, out);
}

// round 15
// speedup vs baseline: 1.0846x; 1.0846x over previous
#include <cuda_runtime.h>
#include <cuda_fp16.h>
#include <math.h>
#include <stdint.h>

// ---------------------------------------------------------------------------
// Problem constants
// ---------------------------------------------------------------------------
#define B_ 2
#define NV 4
#define H_ 240
#define W_ 240
#define H1_ 120
#define W1_ 120
#define D_ 32
#define NPB 131072
#define PT (B_ * NPB)
#define INBASE 70
#define XPAD_H 80             // fp16 feature row, PERMUTED pair layout (160 B)
#define DH 128
#define TM 256                // points per tile (16 warps x 16 rows)
#define NT (PT / TM)          // 1024 tiles (exact)
#define FF_GRID 148
#define FF_THREADS 512        // 16 warps (best measured config)

// Weights: [l][n][144 halves], permuted pair layout, stride 72 words.
// 72 % 32 == 8 -> LDS.64 conflict-free (bank = 8r + 2cp, distinct per half-warp).
#define WS_W 144
#define WS_W32 72
#define WL_W32 (128 * WS_W32)              // 9216 words per layer
#define WS_ALL_BYTES (5 * 128 * WS_W * 2)  // 184320

// Act-in: stride 40 words = natural 80-half row. 40 % 32 == 8 -> LDS.64 OK.
#define ACTIN_W32 40
#define ACTIN_BYTES (TM * ACTIN_W32 * 4)   // 40960

// ---------------------------------------------------------------------------
// Scratch (device globals)
// ---------------------------------------------------------------------------
__device__ __half g_xh[(size_t)PT * XPAD_H];
__device__ __half g_featsTh[(size_t)B_ * NV * H1_ * W1_ * D_];
__device__ __half g_imgsTh[(size_t)B_ * NV * H_ * W_ * 3];
__device__ float  g_proj[B_ * NV * 12];
__device__ __half g_wpadh[5 * 128 * WS_W];

// ---------------------------------------------------------------------------
// helpers
// ---------------------------------------------------------------------------
__device__ __forceinline__ void mma_f16(float (&d)[4], const uint32_t (&a)[4],
                                        const uint32_t (&b)[2]) {
    asm volatile(
        "mma.sync.aligned.m16n8k16.row.col.f32.f16.f16.f32 "
        "{%0,%1,%2,%3}, {%4,%5,%6,%7}, {%8,%9}, {%0,%1,%2,%3};"
        : "+f"(d[0]), "+f"(d[1]), "+f"(d[2]), "+f"(d[3])
        : "r"(a[0]), "r"(a[1]), "r"(a[2]), "r"(a[3]), "r"(b[0]), "r"(b[1]));
}

__device__ __forceinline__ uint32_t smem_u32(const void* p) {
    return (uint32_t)__cvta_generic_to_shared(p);
}

__device__ __forceinline__ void cp16(uint32_t saddr, const void* g) {
    asm volatile("cp.async.cg.shared.global [%0], [%1], 16;" :: "r"(saddr), "l"(g));
}
#define CP_COMMIT() asm volatile("cp.async.commit_group;")
#define CP_WAIT0()  asm volatile("cp.async.wait_group 0;")

__device__ __forceinline__ uint32_t pack_h2(float x, float y) {
    __half2 h = __halves2half2(__float2half_rn(x), __float2half_rn(y));
    return *reinterpret_cast<uint32_t*>(&h);
}

__device__ __forceinline__ void h8_to_f(const uint4& u, float* f) {
    const __half2* h = reinterpret_cast<const __half2*>(&u);
#pragma unroll
    for (int i = 0; i < 4; i++) {
        float2 v = __half22float2(h[i]);
        f[i * 2 + 0] = v.x;
        f[i * 2 + 1] = v.y;
    }
}

// Permutation: within each 16-half (8-word) k-group, new word kt*8+2*cp+s
// holds old word kt*8+cp+4*s. perm80 maps a logical half index to its stored
// position; bijective within each group (covers pad halves 70..79 too).
__device__ __forceinline__ int perm80(int i) {
    int W = i >> 1, h = i & 1;
    int kt = W >> 3, q = W & 7;
    int newW = kt * 8 + ((q < 4) ? (2 * q) : (2 * (q - 4) + 1));
    return newW * 2 + h;
}

// ---------------------------------------------------------------------------
// Kernel 0: projection matrices  P = K @ inv(c2w)[0:3, :]
// ---------------------------------------------------------------------------
__global__ void proj_kernel(const float* __restrict__ cams) {
    int i = threadIdx.x;
    if (i >= B_ * NV) return;
    const float* c = cams + i * 27;
    float K[9];
#pragma unroll
    for (int j = 0; j < 9; j++) K[j] = c[2 + j];
    float m[16];
#pragma unroll
    for (int j = 0; j < 16; j++) m[j] = c[11 + j];

    float inv[16];
    inv[0]  =  m[5]*m[10]*m[15] - m[5]*m[11]*m[14] - m[9]*m[6]*m[15] + m[9]*m[7]*m[14] + m[13]*m[6]*m[11] - m[13]*m[7]*m[10];
    inv[4]  = -m[4]*m[10]*m[15] + m[4]*m[11]*m[14] + m[8]*m[6]*m[15] - m[8]*m[7]*m[14] - m[12]*m[6]*m[11] + m[12]*m[7]*m[10];
    inv[8]  =  m[4]*m[9]*m[15]  - m[4]*m[11]*m[13] - m[8]*m[5]*m[15] + m[8]*m[7]*m[13] + m[12]*m[5]*m[11] - m[12]*m[7]*m[9];
    inv[12] = -m[4]*m[9]*m[14]  + m[4]*m[10]*m[13] + m[8]*m[5]*m[14] - m[8]*m[6]*m[13] - m[12]*m[5]*m[10] + m[12]*m[6]*m[9];
    inv[1]  = -m[1]*m[10]*m[15] + m[1]*m[11]*m[14] + m[9]*m[2]*m[15] - m[9]*m[3]*m[14] - m[13]*m[2]*m[11] + m[13]*m[3]*m[10];
    inv[5]  =  m[0]*m[10]*m[15] - m[0]*m[11]*m[14] - m[8]*m[2]*m[15] + m[8]*m[3]*m[14] + m[12]*m[2]*m[11] - m[12]*m[3]*m[10];
    inv[9]  = -m[0]*m[9]*m[15]  + m[0]*m[11]*m[13] + m[8]*m[1]*m[15] - m[8]*m[3]*m[13] - m[12]*m[1]*m[11] + m[12]*m[3]*m[9];
    inv[13] =  m[0]*m[9]*m[14]  - m[0]*m[10]*m[13] - m[8]*m[1]*m[14] + m[8]*m[2]*m[13] + m[12]*m[1]*m[10] - m[12]*m[2]*m[9];
    inv[2]  =  m[1]*m[6]*m[15]  - m[1]*m[7]*m[14]  - m[5]*m[2]*m[15] + m[5]*m[3]*m[14] + m[13]*m[2]*m[7]  - m[13]*m[3]*m[6];
    inv[6]  = -m[0]*m[6]*m[15]  + m[0]*m[7]*m[14]  + m[4]*m[2]*m[15] - m[4]*m[3]*m[14] - m[12]*m[2]*m[7]  + m[12]*m[3]*m[6];
    inv[10] =  m[0]*m[5]*m[15]  - m[0]*m[7]*m[13]  - m[4]*m[1]*m[15] + m[4]*m[3]*m[13] + m[12]*m[1]*m[7]  - m[12]*m[3]*m[5];
    inv[14] = -m[0]*m[5]*m[14]  + m[0]*m[6]*m[13]  + m[4]*m[1]*m[14] - m[4]*m[2]*m[13] - m[12]*m[1]*m[6]  + m[12]*m[2]*m[5];
    inv[3]  = -m[1]*m[6]*m[11]  + m[1]*m[7]*m[10]  + m[5]*m[2]*m[11] - m[5]*m[3]*m[10] - m[9]*m[2]*m[7]   + m[9]*m[3]*m[6];
    inv[7]  =  m[0]*m[6]*m[11]  - m[0]*m[7]*m[10]  - m[4]*m[2]*m[11] + m[4]*m[3]*m[10] + m[8]*m[2]*m[7]   - m[8]*m[3]*m[6];
    inv[11] = -m[0]*m[5]*m[11]  + m[0]*m[7]*m[9]   + m[4]*m[1]*m[11] - m[4]*m[3]*m[9]  - m[8]*m[1]*m[7]   + m[8]*m[3]*m[5];
    inv[15] =  m[0]*m[5]*m[10]  - m[0]*m[6]*m[9]   - m[4]*m[1]*m[10] + m[4]*m[2]*m[9]  + m[8]*m[1]*m[6]   - m[8]*m[2]*m[5];

    float det = m[0]*inv[0] + m[1]*inv[4] + m[2]*inv[8] + m[3]*inv[12];
    float id = 1.0f / det;
#pragma unroll
    for (int j = 0; j < 16; j++) inv[j] *= id;

#pragma unroll
    for (int r = 0; r < 3; r++) {
#pragma unroll
        for (int cc = 0; cc < 4; cc++) {
            float s = K[r*3+0]*inv[0*4+cc] + K[r*3+1]*inv[1*4+cc] + K[r*3+2]*inv[2*4+cc];
            g_proj[i*12 + r*4 + cc] = s;
        }
    }
}

// ---------------------------------------------------------------------------
// Weight prep: fp16, [l][n][144 halves] permuted-pair layout.
// stored half hw: w=hw/2,h=hw%2; if w<64: kt=w>>3,t=w&7,cp=t>>1,s=t&1,
// k=(kt*8+cp+4*s)*2+h, value = W_l[k][n]; else 0.
// ---------------------------------------------------------------------------
__global__ void wprep_kernel(const float* __restrict__ w0, const float* __restrict__ w1,
                             const float* __restrict__ w2, const float* __restrict__ w3,
                             const float* __restrict__ w4) {
    int o = blockIdx.x * blockDim.x + threadIdx.x;
    if (o >= 5 * 128 * WS_W) return;
    int l = o / (128 * WS_W);
    int rem = o - l * 128 * WS_W;
    int n = rem / WS_W;
    int hw = rem - n * WS_W;
    int w = hw >> 1, h = hw & 1;
    float v = 0.f;
    if (w < 64) {
        int kt = w >> 3, t = w & 7;
        int cp = t >> 1, s = t & 1;
        int k = (kt * 8 + cp + 4 * s) * 2 + h;
        if (l == 0) {
            if (k < INBASE) v = w0[k * DH + n];
        } else {
            const float* wl = (l == 1) ? w1 : (l == 2) ? w2 : (l == 3) ? w3 : w4;
            v = wl[k * DH + n];
        }
    }
    g_wpadh[o] = __float2half_rn(v);
}

// ---------------------------------------------------------------------------
// Transposes to channel-last fp16
// ---------------------------------------------------------------------------
__global__ void tfeat_kernel(const float* __restrict__ f) {
    int o = blockIdx.x * blockDim.x + threadIdx.x;
    if (o >= B_ * NV * H1_ * W1_ * D_) return;
    int c = o & (D_ - 1);
    int rest = o >> 5;
    int x = rest % W1_;
    int t2 = rest / W1_;
    int y = t2 % H1_;
    int bv = t2 / H1_;
    g_featsTh[o] = __float2half_rn(f[((size_t)(bv * D_ + c)) * (H1_ * W1_) + y * W1_ + x]);
}

__global__ void timg_kernel(const float* __restrict__ im) {
    int o = blockIdx.x * blockDim.x + threadIdx.x;
    if (o >= B_ * NV * H_ * W_ * 3) return;
    int c = o % 3;
    int rest = o / 3;
    int x = rest % W_;
    int t2 = rest / W_;
    int y = t2 % H_;
    int bv = t2 / H_;
    g_imgsTh[o] = __float2half_rn(im[((size_t)(bv * 3 + c)) * (H_ * W_) + y * W_ + x]);
}

// ---------------------------------------------------------------------------
// Kernel 1: quad featurize (4 threads/point) -> g_xh [PT][80], permuted layout
// ---------------------------------------------------------------------------
__global__ void __launch_bounds__(256) featurize_kernel(const float* __restrict__ xyz) {
    int t = blockIdx.x * blockDim.x + threadIdx.x;
    int gp = t >> 2;
    int q  = t & 3;
    if (gp >= PT) return;
    int b = gp / NPB;

    float X = xyz[(size_t)gp * 3 + 0];
    float Y = xyz[(size_t)gp * 3 + 1];
    float Z = xyz[(size_t)gp * 3 + 2];

    float fs[8], fq[8];
#pragma unroll
    for (int i = 0; i < 8; i++) { fs[i] = 0.f; fq[i] = 0.f; }
    float rs = 0.f, rq = 0.f;
    float s = 0.f;

    const float SX = (float)(W1_ - 1) / (float)(W_ - 1);
    const float SY = (float)(H1_ - 1) / (float)(H_ - 1);

#pragma unroll
    for (int v = 0; v < NV; v++) {
        const float* Pm = &g_proj[(b * NV + v) * 12];
        float pxn = Pm[0]*X + Pm[1]*Y + Pm[2]*Z  + Pm[3];
        float pyn = Pm[4]*X + Pm[5]*Y + Pm[6]*Z  + Pm[7];
        float pz  = Pm[8]*X + Pm[9]*Y + Pm[10]*Z + Pm[11];
        float d = fmaxf(pz, 1e-8f);
        float px = pxn / d;
        float py = pyn / d;
        bool inb = (pz > 1e-4f) && (px >= 0.f) && (px <= (float)(W_ - 1))
                                && (py >= 0.f) && (py <= (float)(H_ - 1));
        if (!inb) continue;
        s += 1.f;

        if (q < 3) {
            float x0f = floorf(px), y0f = floorf(py);
            float wx = px - x0f, wy = py - y0f;
            int x0 = (int)x0f;
            int y0 = (int)y0f;
            int x1 = min(x0 + 1, W_ - 1);
            int y1 = min(y0 + 1, H_ - 1);
            float w00 = (1.f - wx) * (1.f - wy);
            float w01 = wx * (1.f - wy);
            float w10 = (1.f - wx) * wy;
            float w11 = wx * wy;
            const __half* ib = g_imgsTh + (size_t)(b * NV + v) * H_ * W_ * 3 + q;
            float val = __half2float(ib[(size_t)(y0 * W_ + x0) * 3]) * w00
                      + __half2float(ib[(size_t)(y0 * W_ + x1) * 3]) * w01
                      + __half2float(ib[(size_t)(y1 * W_ + x0) * 3]) * w10
                      + __half2float(ib[(size_t)(y1 * W_ + x1) * 3]) * w11;
            rs += val;
            rq += val * val;
        }

        {
            float fx = px * SX;
            float fy = py * SY;
            float x0f = floorf(fx), y0f = floorf(fy);
            float wx = fx - x0f, wy = fy - y0f;
            int x0 = (int)x0f;
            int y0 = (int)y0f;
            int x1 = min(x0 + 1, W1_ - 1);
            int y1 = min(y0 + 1, H1_ - 1);
            float w00 = (1.f - wx) * (1.f - wy);
            float w01 = wx * (1.f - wy);
            float w10 = (1.f - wx) * wy;
            float w11 = wx * wy;
            const __half* fb = g_featsTh + (size_t)(b * NV + v) * H1_ * W1_ * D_ + q * 8;
            uint4 u00 = *reinterpret_cast<const uint4*>(fb + (size_t)(y0 * W1_ + x0) * D_);
            uint4 u01 = *reinterpret_cast<const uint4*>(fb + (size_t)(y0 * W1_ + x1) * D_);
            uint4 u10 = *reinterpret_cast<const uint4*>(fb + (size_t)(y1 * W1_ + x0) * D_);
            uint4 u11 = *reinterpret_cast<const uint4*>(fb + (size_t)(y1 * W1_ + x1) * D_);
            float a[8], bb[8], cc[8], dd[8];
            h8_to_f(u00, a); h8_to_f(u01, bb); h8_to_f(u10, cc); h8_to_f(u11, dd);
#pragma unroll
            for (int j = 0; j < 8; j++) {
                float vv = a[j]*w00 + bb[j]*w01 + cc[j]*w10 + dd[j]*w11;
                fs[j] += vv;
                fq[j] += vv * vv;
            }
        }
    }

    float denom = s + 1e-6f;
    float invd = 1.f / denom;
    float alpha = s * invd;
    float two_m_a = 2.f - alpha;
    __half* xo = g_xh + (size_t)gp * XPAD_H;

    if (q < 3) {
        float m  = rs * invd;
        float e2 = rq * invd;
        xo[perm80(q)]      = __float2half_rn(m);
        xo[perm80(35 + q)] = __float2half_rn(e2 - two_m_a * m * m);
    }
#pragma unroll
    for (int j = 0; j < 8; j++) {
        int i = 3 + q * 8 + j;
        float m  = fs[j] * invd;
        float e2 = fq[j] * invd;
        xo[perm80(i)]      = __float2half_rn(m);
        xo[perm80(35 + i)] = __float2half_rn(e2 - two_m_a * m * m);
    }
    if (q == 0) {
#pragma unroll
        for (int j = 70; j < XPAD_H; j++) xo[perm80(j)] = __float2half_rn(0.f);
    }
}

// ---------------------------------------------------------------------------
// Kernel 2: fully-fused register-resident MLP, LDS.64 fragment loads.
// Persistent, 148 blocks x 512 threads (16 warps). Tile = 256 points.
// ---------------------------------------------------------------------------
__global__ void __launch_bounds__(FF_THREADS, 1) mlp_ff_kernel(
    const float* __restrict__ b0, const float* __restrict__ b1,
    const float* __restrict__ b2, const float* __restrict__ b3,
    const float* __restrict__ b4,
    const float* __restrict__ w5, const float* __restrict__ b5,
    const float* __restrict__ dw, const float* __restrict__ db,
    float* __restrict__ out) {

    extern __shared__ char smem[];
    uint32_t* actin = reinterpret_cast<uint32_t*>(smem);                 // ACTIN_BYTES
    uint32_t* wsm   = reinterpret_cast<uint32_t*>(smem + ACTIN_BYTES);   // WS_ALL_BYTES
    float* bias = reinterpret_cast<float*>(smem + ACTIN_BYTES + WS_ALL_BYTES);
    float* w5s  = bias + 5 * DH;
    float* dws  = w5s + DH * 3;

    const int tid  = threadIdx.x;
    const int lane = tid & 31;
    const int warp = tid >> 5;
    const int r  = lane >> 2;
    const int cp = lane & 3;
    const int R0 = warp * 16 + r;
    const int R1 = R0 + 8;

    const uint32_t s_act = smem_u32(actin);
    const uint32_t s_w   = smem_u32(wsm);

    // stage all 5 weight layers + first act tile (flat contiguous copies)
    for (int i = tid; i < WS_ALL_BYTES / 16; i += FF_THREADS)
        cp16(s_w + (uint32_t)i * 16, g_wpadh + i * 8);
    int tile = blockIdx.x;
    {
        const __half* gx = g_xh + (size_t)tile * TM * XPAD_H;
        for (int i = tid; i < ACTIN_BYTES / 16; i += FF_THREADS)
            cp16(s_act + (uint32_t)i * 16, gx + i * 8);
    }
    CP_COMMIT();

    if (tid < DH) {
        bias[0 * DH + tid] = b0[tid];
        bias[1 * DH + tid] = b1[tid];
        bias[2 * DH + tid] = b2[tid];
        bias[3 * DH + tid] = b3[tid];
        bias[4 * DH + tid] = b4[tid];
        dws[tid] = dw[tid];
    }
    for (int i = tid; i < DH * 3; i += FF_THREADS) w5s[i] = w5[i];
    const float db0 = db[0];
    const float b50 = b5[0], b51 = b5[1], b52 = b5[2];

    float acc[16][4];
    uint32_t h[32];

    for (; tile < NT; tile += FF_GRID) {
        CP_WAIT0();
        __syncthreads();

        // ---- layer 0: A from actin (K=80 -> 5 ksteps), LDS.64 pairs ----
#pragma unroll
        for (int j = 0; j < 16; j++)
#pragma unroll
            for (int d = 0; d < 4; d++) acc[j][d] = 0.f;
#pragma unroll
        for (int kt = 0; kt < 5; kt++) {
            uint32_t a[4];
            {
                uint2 u0 = *reinterpret_cast<const uint2*>(
                    &actin[R0 * ACTIN_W32 + kt * 8 + cp * 2]);
                uint2 u1 = *reinterpret_cast<const uint2*>(
                    &actin[R1 * ACTIN_W32 + kt * 8 + cp * 2]);
                a[0] = u0.x; a[2] = u0.y;
                a[1] = u1.x; a[3] = u1.y;
            }
#pragma unroll
            for (int j = 0; j < 16; j++) {
                uint2 bu = *reinterpret_cast<const uint2*>(
                    &wsm[(j * 8 + r) * WS_W32 + kt * 8 + cp * 2]);
                uint32_t bfr[2] = {bu.x, bu.y};
                mma_f16(acc[j], a, bfr);
            }
        }

        // pf: bias, sigma head partials, convert to h
        {
            float sp0 = 0.f, sp1 = 0.f;
#pragma unroll
            for (int j = 0; j < 16; j++) {
                int c0 = j * 8 + cp * 2;
                float bv0 = bias[c0], bv1 = bias[c0 + 1];
                float v0 = acc[j][0] + bv0, v1 = acc[j][1] + bv1;
                float v2 = acc[j][2] + bv0, v3 = acc[j][3] + bv1;
                float d0 = dws[c0], d1 = dws[c0 + 1];
                sp0 = fmaf(v0, d0, fmaf(v1, d1, sp0));
                sp1 = fmaf(v2, d0, fmaf(v3, d1, sp1));
                h[j]      = pack_h2(v0, v1);
                h[16 + j] = pack_h2(v2, v3);
            }
            sp0 += __shfl_xor_sync(0xffffffff, sp0, 1);
            sp0 += __shfl_xor_sync(0xffffffff, sp0, 2);
            sp1 += __shfl_xor_sync(0xffffffff, sp1, 1);
            sp1 += __shfl_xor_sync(0xffffffff, sp1, 2);
            if (cp == 0) {
                size_t p = (size_t)tile * TM;
                out[(p + R0) * 4 + 3] = fmaxf(sp0 + db0, 0.f);
                out[(p + R1) * 4 + 3] = fmaxf(sp1 + db0, 0.f);
            }
        }

        __syncthreads();   // all warps done reading actin
        {
            int nt2 = tile + FF_GRID;
            if (nt2 < NT) {
                const __half* gx = g_xh + (size_t)nt2 * TM * XPAD_H;
                for (int i = tid; i < ACTIN_BYTES / 16; i += FF_THREADS)
                    cp16(s_act + (uint32_t)i * 16, gx + i * 8);
            }
        }
        CP_COMMIT();

        // ---- layers 1..4 (register chain; LDS.64 B-fragments) ----
#pragma unroll 1
        for (int l = 1; l < 5; l++) {
            const uint32_t* wp = wsm + l * WL_W32;
            const float* bl = bias + l * DH;
#pragma unroll
            for (int j = 0; j < 16; j++)
#pragma unroll
                for (int d = 0; d < 4; d++) acc[j][d] = 0.f;
#pragma unroll
            for (int kt = 0; kt < 8; kt++) {
                uint32_t a[4];
                a[0] = h[2 * kt];
                a[1] = h[16 + 2 * kt];
                a[2] = h[2 * kt + 1];
                a[3] = h[16 + 2 * kt + 1];
#pragma unroll
                for (int j = 0; j < 16; j++) {
                    uint2 bu = *reinterpret_cast<const uint2*>(
                        &wp[(j * 8 + r) * WS_W32 + kt * 8 + cp * 2]);
                    uint32_t bfr[2] = {bu.x, bu.y};
                    mma_f16(acc[j], a, bfr);
                }
            }
            if (l < 4) {
#pragma unroll
                for (int j = 0; j < 16; j++) {
                    int c0 = j * 8 + cp * 2;
                    float bv0 = bl[c0], bv1 = bl[c0 + 1];
                    float v0 = acc[j][0] + bv0, v1 = acc[j][1] + bv1;
                    float v2 = acc[j][2] + bv0, v3 = acc[j][3] + bv1;
                    v0 = v0 > 0.f ? v0 : 0.01f * v0;
                    v1 = v1 > 0.f ? v1 : 0.01f * v1;
                    v2 = v2 > 0.f ? v2 : 0.01f * v2;
                    v3 = v3 > 0.f ? v3 : 0.01f * v3;
                    h[j]      = pack_h2(v0, v1);
                    h[16 + j] = pack_h2(v2, v3);
                }
            } else {
                float ra0 = 0.f, ra1 = 0.f, ra2 = 0.f;
                float rb0 = 0.f, rb1 = 0.f, rb2 = 0.f;
#pragma unroll
                for (int j = 0; j < 16; j++) {
                    int c0 = j * 8 + cp * 2;
                    float bv0 = bl[c0], bv1 = bl[c0 + 1];
                    float v0 = acc[j][0] + bv0, v1 = acc[j][1] + bv1;
                    float v2 = acc[j][2] + bv0, v3 = acc[j][3] + bv1;
                    v0 = v0 > 0.f ? v0 : 0.01f * v0;
                    v1 = v1 > 0.f ? v1 : 0.01f * v1;
                    v2 = v2 > 0.f ? v2 : 0.01f * v2;
                    v3 = v3 > 0.f ? v3 : 0.01f * v3;
                    float w00 = w5s[c0 * 3 + 0], w01 = w5s[c0 * 3 + 1], w02 = w5s[c0 * 3 + 2];
                    float w10 = w5s[(c0 + 1) * 3 + 0], w11 = w5s[(c0 + 1) * 3 + 1], w12 = w5s[(c0 + 1) * 3 + 2];
                    ra0 = fmaf(v0, w00, fmaf(v1, w10, ra0));
                    ra1 = fmaf(v0, w01, fmaf(v1, w11, ra1));
                    ra2 = fmaf(v0, w02, fmaf(v1, w12, ra2));
                    rb0 = fmaf(v2, w00, fmaf(v3, w10, rb0));
                    rb1 = fmaf(v2, w01, fmaf(v3, w11, rb1));
                    rb2 = fmaf(v2, w02, fmaf(v3, w12, rb2));
                }
                ra0 += __shfl_xor_sync(0xffffffff, ra0, 1);
                ra0 += __shfl_xor_sync(0xffffffff, ra0, 2);
                ra1 += __shfl_xor_sync(0xffffffff, ra1, 1);
                ra1 += __shfl_xor_sync(0xffffffff, ra1, 2);
                ra2 += __shfl_xor_sync(0xffffffff, ra2, 1);
                ra2 += __shfl_xor_sync(0xffffffff, ra2, 2);
                rb0 += __shfl_xor_sync(0xffffffff, rb0, 1);
                rb0 += __shfl_xor_sync(0xffffffff, rb0, 2);
                rb1 += __shfl_xor_sync(0xffffffff, rb1, 1);
                rb1 += __shfl_xor_sync(0xffffffff, rb1, 2);
                rb2 += __shfl_xor_sync(0xffffffff, rb2, 1);
                rb2 += __shfl_xor_sync(0xffffffff, rb2, 2);
                if (cp == 0) {
                    size_t p = (size_t)tile * TM;
                    size_t o0 = (p + R0) * 4, o1 = (p + R1) * 4;
                    out[o0 + 0] = tanhf(ra0 + b50);
                    out[o0 + 1] = tanhf(ra1 + b51);
                    out[o0 + 2] = tanhf(ra2 + b52);
                    out[o1 + 0] = tanhf(rb0 + b50);
                    out[o1 + 1] = tanhf(rb1 + b51);
                    out[o1 + 2] = tanhf(rb2 + b52);
                }
            }
        }
    }
}

// ---------------------------------------------------------------------------
// Launch
// ---------------------------------------------------------------------------
extern "C" void kernel_launch(void* const* d_in, const int* in_sizes, int n_in,
                              void* d_out, int out_size) {
    const float* xyz       = (const float*)d_in[0];
    const float* src_imgs  = (const float*)d_in[2];
    const float* src_cams  = (const float*)d_in[3];
    const float* src_feats = (const float*)d_in[4];
    const float* w0 = (const float*)d_in[5];
    const float* b0 = (const float*)d_in[6];
    const float* w1 = (const float*)d_in[7];
    const float* b1 = (const float*)d_in[8];
    const float* w2 = (const float*)d_in[9];
    const float* b2 = (const float*)d_in[10];
    const float* w3 = (const float*)d_in[11];
    const float* b3 = (const float*)d_in[12];
    const float* w4 = (const float*)d_in[13];
    const float* b4 = (const float*)d_in[14];
    const float* w5 = (const float*)d_in[15];
    const float* b5 = (const float*)d_in[16];
    const float* dw = (const float*)d_in[17];
    const float* db = (const float*)d_in[18];
    float* out = (float*)d_out;

    const int smem_bytes = ACTIN_BYTES + WS_ALL_BYTES
                         + (5 * DH + DH * 3 + DH) * (int)sizeof(float);
    cudaFuncSetAttribute(mlp_ff_kernel,
                         cudaFuncAttributeMaxDynamicSharedMemorySize, smem_bytes);

    proj_kernel<<<1, 32>>>(src_cams);
    wprep_kernel<<<(5 * 128 * WS_W + 255) / 256, 256>>>(w0, w1, w2, w3, w4);
    tfeat_kernel<<<(B_ * NV * H1_ * W1_ * D_) / 256, 256>>>(src_feats);
    timg_kernel<<<(B_ * NV * H_ * W_ * 3 + 255) / 256, 256>>>(src_imgs);
    featurize_kernel<<<(PT * 4) / 256, 256>>>(xyz);
    mlp_ff_kernel<<<FF_GRID, FF_THREADS, smem_bytes>>>(b0, b1, b2, b3, b4,
                                                       w5, b5, dw, db, out);
}

// round 16
// speedup vs baseline: 1.2249x; 1.1294x over previous
#include <cuda_runtime.h>
#include <cuda_fp16.h>
#include <math.h>
#include <stdint.h>

// ---------------------------------------------------------------------------
// Problem constants
// ---------------------------------------------------------------------------
#define B_ 2
#define NV 4
#define H_ 240
#define W_ 240
#define H1_ 120
#define W1_ 120
#define D_ 32
#define NPB 131072
#define PT (B_ * NPB)
#define INBASE 70
#define DH 128
#define TM 128                 // points per tile (8 MLP warps x 16 rows)
#define NT (PT / TM)           // 2048 tiles (exact)
#define FF_GRID 148
#define FF_THREADS 384         // 12 warps: 0-7 MLP, 8-11 featurize. reg cap 170.

// Weights: [l][n][144 halves], permuted pair layout, stride 72 words.
// 72 % 32 == 8 -> LDS.64 conflict-free.
#define WS_W 144
#define WS_W32 72
#define WL_W32 (128 * WS_W32)
#define WS_ALL_BYTES (5 * 128 * WS_W * 2)  // 184320

// Act tile: 128 rows x 40 words (80 halves, permuted pairs). 40 % 32 == 8 -> LDS.64 OK.
#define ACT_W32 40
#define ACT_TILE_BYTES (TM * ACT_W32 * 4)  // 20480, double buffered

// ---------------------------------------------------------------------------
// Scratch (device globals)
// ---------------------------------------------------------------------------
__device__ __half g_featsTh[(size_t)B_ * NV * H1_ * W1_ * D_];
__device__ __half g_imgsTh[(size_t)B_ * NV * H_ * W_ * 3];
__device__ float  g_proj[B_ * NV * 12];
__device__ __half g_wpadh[5 * 128 * WS_W];

// ---------------------------------------------------------------------------
// helpers
// ---------------------------------------------------------------------------
__device__ __forceinline__ void mma_f16(float (&d)[4], const uint32_t (&a)[4],
                                        const uint32_t (&b)[2]) {
    asm volatile(
        "mma.sync.aligned.m16n8k16.row.col.f32.f16.f16.f32 "
        "{%0,%1,%2,%3}, {%4,%5,%6,%7}, {%8,%9}, {%0,%1,%2,%3};"
        : "+f"(d[0]), "+f"(d[1]), "+f"(d[2]), "+f"(d[3])
        : "r"(a[0]), "r"(a[1]), "r"(a[2]), "r"(a[3]), "r"(b[0]), "r"(b[1]));
}

__device__ __forceinline__ uint32_t smem_u32(const void* p) {
    return (uint32_t)__cvta_generic_to_shared(p);
}

__device__ __forceinline__ void cp16(uint32_t saddr, const void* g) {
    asm volatile("cp.async.cg.shared.global [%0], [%1], 16;" :: "r"(saddr), "l"(g));
}
#define CP_COMMIT() asm volatile("cp.async.commit_group;")
#define CP_WAIT0()  asm volatile("cp.async.wait_group 0;")

__device__ __forceinline__ uint32_t pack_h2(float x, float y) {
    __half2 h = __halves2half2(__float2half_rn(x), __float2half_rn(y));
    return *reinterpret_cast<uint32_t*>(&h);
}

__device__ __forceinline__ void h8_to_f(const uint4& u, float* f) {
    const __half2* h = reinterpret_cast<const __half2*>(&u);
#pragma unroll
    for (int i = 0; i < 4; i++) {
        float2 v = __half22float2(h[i]);
        f[i * 2 + 0] = v.x;
        f[i * 2 + 1] = v.y;
    }
}

// ---------------------------------------------------------------------------
// Kernel 0: projection matrices  P = K @ inv(c2w)[0:3, :]
// ---------------------------------------------------------------------------
__global__ void proj_kernel(const float* __restrict__ cams) {
    int i = threadIdx.x;
    if (i >= B_ * NV) return;
    const float* c = cams + i * 27;
    float K[9];
#pragma unroll
    for (int j = 0; j < 9; j++) K[j] = c[2 + j];
    float m[16];
#pragma unroll
    for (int j = 0; j < 16; j++) m[j] = c[11 + j];

    float inv[16];
    inv[0]  =  m[5]*m[10]*m[15] - m[5]*m[11]*m[14] - m[9]*m[6]*m[15] + m[9]*m[7]*m[14] + m[13]*m[6]*m[11] - m[13]*m[7]*m[10];
    inv[4]  = -m[4]*m[10]*m[15] + m[4]*m[11]*m[14] + m[8]*m[6]*m[15] - m[8]*m[7]*m[14] - m[12]*m[6]*m[11] + m[12]*m[7]*m[10];
    inv[8]  =  m[4]*m[9]*m[15]  - m[4]*m[11]*m[13] - m[8]*m[5]*m[15] + m[8]*m[7]*m[13] + m[12]*m[5]*m[11] - m[12]*m[7]*m[9];
    inv[12] = -m[4]*m[9]*m[14]  + m[4]*m[10]*m[13] + m[8]*m[5]*m[14] - m[8]*m[6]*m[13] - m[12]*m[5]*m[10] + m[12]*m[6]*m[9];
    inv[1]  = -m[1]*m[10]*m[15] + m[1]*m[11]*m[14] + m[9]*m[2]*m[15] - m[9]*m[3]*m[14] - m[13]*m[2]*m[11] + m[13]*m[3]*m[10];
    inv[5]  =  m[0]*m[10]*m[15] - m[0]*m[11]*m[14] - m[8]*m[2]*m[15] + m[8]*m[3]*m[14] + m[12]*m[2]*m[11] - m[12]*m[3]*m[10];
    inv[9]  = -m[0]*m[9]*m[15]  + m[0]*m[11]*m[13] + m[8]*m[1]*m[15] - m[8]*m[3]*m[13] - m[12]*m[1]*m[11] + m[12]*m[3]*m[9];
    inv[13] =  m[0]*m[9]*m[14]  - m[0]*m[10]*m[13] - m[8]*m[1]*m[14] + m[8]*m[2]*m[13] + m[12]*m[1]*m[10] - m[12]*m[2]*m[9];
    inv[2]  =  m[1]*m[6]*m[15]  - m[1]*m[7]*m[14]  - m[5]*m[2]*m[15] + m[5]*m[3]*m[14] + m[13]*m[2]*m[7]  - m[13]*m[3]*m[6];
    inv[6]  = -m[0]*m[6]*m[15]  + m[0]*m[7]*m[14]  + m[4]*m[2]*m[15] - m[4]*m[3]*m[14] - m[12]*m[2]*m[7]  + m[12]*m[3]*m[6];
    inv[10] =  m[0]*m[5]*m[15]  - m[0]*m[7]*m[13]  - m[4]*m[1]*m[15] + m[4]*m[3]*m[13] + m[12]*m[1]*m[7]  - m[12]*m[3]*m[5];
    inv[14] = -m[0]*m[5]*m[14]  + m[0]*m[6]*m[13]  + m[4]*m[1]*m[14] - m[4]*m[2]*m[13] - m[12]*m[1]*m[6]  + m[12]*m[2]*m[5];
    inv[3]  = -m[1]*m[6]*m[11]  + m[1]*m[7]*m[10]  + m[5]*m[2]*m[11] - m[5]*m[3]*m[10] - m[9]*m[2]*m[7]   + m[9]*m[3]*m[6];
    inv[7]  =  m[0]*m[6]*m[11]  - m[0]*m[7]*m[10]  - m[4]*m[2]*m[11] + m[4]*m[3]*m[10] + m[8]*m[2]*m[7]   - m[8]*m[3]*m[6];
    inv[11] = -m[0]*m[5]*m[11]  + m[0]*m[7]*m[9]   + m[4]*m[1]*m[11] - m[4]*m[3]*m[9]  - m[8]*m[1]*m[7]   + m[8]*m[3]*m[5];
    inv[15] =  m[0]*m[5]*m[10]  - m[0]*m[6]*m[9]   - m[4]*m[1]*m[10] + m[4]*m[2]*m[9]  + m[8]*m[1]*m[6]   - m[8]*m[2]*m[5];

    float det = m[0]*inv[0] + m[1]*inv[4] + m[2]*inv[8] + m[3]*inv[12];
    float id = 1.0f / det;
#pragma unroll
    for (int j = 0; j < 16; j++) inv[j] *= id;

#pragma unroll
    for (int r = 0; r < 3; r++) {
#pragma unroll
        for (int cc = 0; cc < 4; cc++) {
            float s = K[r*3+0]*inv[0*4+cc] + K[r*3+1]*inv[1*4+cc] + K[r*3+2]*inv[2*4+cc];
            g_proj[i*12 + r*4 + cc] = s;
        }
    }
}

// ---------------------------------------------------------------------------
// Weight prep: fp16, [l][n][144 halves] permuted-pair layout (round-15 layout)
// ---------------------------------------------------------------------------
__global__ void wprep_kernel(const float* __restrict__ w0, const float* __restrict__ w1,
                             const float* __restrict__ w2, const float* __restrict__ w3,
                             const float* __restrict__ w4) {
    int o = blockIdx.x * blockDim.x + threadIdx.x;
    if (o >= 5 * 128 * WS_W) return;
    int l = o / (128 * WS_W);
    int rem = o - l * 128 * WS_W;
    int n = rem / WS_W;
    int hw = rem - n * WS_W;
    int w = hw >> 1, h = hw & 1;
    float v = 0.f;
    if (w < 64) {
        int kt = w >> 3, t = w & 7;
        int cp = t >> 1, s = t & 1;
        int k = (kt * 8 + cp + 4 * s) * 2 + h;
        if (l == 0) {
            if (k < INBASE) v = w0[k * DH + n];
        } else {
            const float* wl = (l == 1) ? w1 : (l == 2) ? w2 : (l == 3) ? w3 : w4;
            v = wl[k * DH + n];
        }
    }
    g_wpadh[o] = __float2half_rn(v);
}

// ---------------------------------------------------------------------------
// Transposes to channel-last fp16
// ---------------------------------------------------------------------------
__global__ void tfeat_kernel(const float* __restrict__ f) {
    int o = blockIdx.x * blockDim.x + threadIdx.x;
    if (o >= B_ * NV * H1_ * W1_ * D_) return;
    int c = o & (D_ - 1);
    int rest = o >> 5;
    int x = rest % W1_;
    int t2 = rest / W1_;
    int y = t2 % H1_;
    int bv = t2 / H1_;
    g_featsTh[o] = __float2half_rn(f[((size_t)(bv * D_ + c)) * (H1_ * W1_) + y * W1_ + x]);
}

__global__ void timg_kernel(const float* __restrict__ im) {
    int o = blockIdx.x * blockDim.x + threadIdx.x;
    if (o >= B_ * NV * H_ * W_ * 3) return;
    int c = o % 3;
    int rest = o / 3;
    int x = rest % W_;
    int t2 = rest / W_;
    int y = t2 % H_;
    int bv = t2 / H_;
    g_imgsTh[o] = __float2half_rn(im[((size_t)(bv * 3 + c)) * (H_ * W_) + y * W_ + x]);
}

// ---------------------------------------------------------------------------
// Full-point featurize (one thread = one point) -> SMEM row, permuted layout.
// dstrow: uint32_t* to the point's 40-word row in the act buffer.
// ---------------------------------------------------------------------------
__device__ void featurize_point(int gp, const float* __restrict__ xyz,
                                uint32_t* __restrict__ dstrow) {
    int b = gp / NPB;
    float X = xyz[(size_t)gp * 3 + 0];
    float Y = xyz[(size_t)gp * 3 + 1];
    float Z = xyz[(size_t)gp * 3 + 2];

    float sum[35], sq[35];
#pragma unroll
    for (int i = 0; i < 35; i++) { sum[i] = 0.f; sq[i] = 0.f; }
    float s = 0.f;

    const float SX = (float)(W1_ - 1) / (float)(W_ - 1);
    const float SY = (float)(H1_ - 1) / (float)(H_ - 1);

#pragma unroll 1
    for (int v = 0; v < NV; v++) {
        const float* Pm = &g_proj[(b * NV + v) * 12];
        float pxn = Pm[0]*X + Pm[1]*Y + Pm[2]*Z  + Pm[3];
        float pyn = Pm[4]*X + Pm[5]*Y + Pm[6]*Z  + Pm[7];
        float pz  = Pm[8]*X + Pm[9]*Y + Pm[10]*Z + Pm[11];
        float d = fmaxf(pz, 1e-8f);
        float px = pxn / d;
        float py = pyn / d;
        bool inb = (pz > 1e-4f) && (px >= 0.f) && (px <= (float)(W_ - 1))
                                && (py >= 0.f) && (py <= (float)(H_ - 1));
        if (!inb) continue;
        s += 1.f;

        {   // image bilinear, 3 channels
            float x0f = floorf(px), y0f = floorf(py);
            float wx = px - x0f, wy = py - y0f;
            int x0 = (int)x0f;
            int y0 = (int)y0f;
            int x1 = min(x0 + 1, W_ - 1);
            int y1 = min(y0 + 1, H_ - 1);
            float w00 = (1.f - wx) * (1.f - wy);
            float w01 = wx * (1.f - wy);
            float w10 = (1.f - wx) * wy;
            float w11 = wx * wy;
            const __half* ib = g_imgsTh + (size_t)(b * NV + v) * H_ * W_ * 3;
            const __half* p00 = ib + (size_t)(y0 * W_ + x0) * 3;
            const __half* p01 = ib + (size_t)(y0 * W_ + x1) * 3;
            const __half* p10 = ib + (size_t)(y1 * W_ + x0) * 3;
            const __half* p11 = ib + (size_t)(y1 * W_ + x1) * 3;
#pragma unroll
            for (int c = 0; c < 3; c++) {
                float val = __half2float(p00[c]) * w00 + __half2float(p01[c]) * w01
                          + __half2float(p10[c]) * w10 + __half2float(p11[c]) * w11;
                sum[c] += val;
                sq[c]  += val * val;
            }
        }

        {   // feature bilinear, 32 channels in 4 segments of 8
            float fx = px * SX;
            float fy = py * SY;
            float x0f = floorf(fx), y0f = floorf(fy);
            float wx = fx - x0f, wy = fy - y0f;
            int x0 = (int)x0f;
            int y0 = (int)y0f;
            int x1 = min(x0 + 1, W1_ - 1);
            int y1 = min(y0 + 1, H1_ - 1);
            float w00 = (1.f - wx) * (1.f - wy);
            float w01 = wx * (1.f - wy);
            float w10 = (1.f - wx) * wy;
            float w11 = wx * wy;
            const __half* fb = g_featsTh + (size_t)(b * NV + v) * H1_ * W1_ * D_;
            const __half* r00 = fb + (size_t)(y0 * W1_ + x0) * D_;
            const __half* r01 = fb + (size_t)(y0 * W1_ + x1) * D_;
            const __half* r10 = fb + (size_t)(y1 * W1_ + x0) * D_;
            const __half* r11 = fb + (size_t)(y1 * W1_ + x1) * D_;
#pragma unroll
            for (int seg = 0; seg < 4; seg++) {
                uint4 u00 = *reinterpret_cast<const uint4*>(r00 + seg * 8);
                uint4 u01 = *reinterpret_cast<const uint4*>(r01 + seg * 8);
                uint4 u10 = *reinterpret_cast<const uint4*>(r10 + seg * 8);
                uint4 u11 = *reinterpret_cast<const uint4*>(r11 + seg * 8);
                float a[8], bb[8], cc[8], dd[8];
                h8_to_f(u00, a); h8_to_f(u01, bb); h8_to_f(u10, cc); h8_to_f(u11, dd);
#pragma unroll
                for (int j = 0; j < 8; j++) {
                    float vv = a[j]*w00 + bb[j]*w01 + cc[j]*w10 + dd[j]*w11;
                    sum[3 + seg * 8 + j] += vv;
                    sq[3 + seg * 8 + j]  += vv * vv;
                }
            }
        }
    }

    float denom = s + 1e-6f;
    float invd = 1.f / denom;
    float alpha = s * invd;
    float two_m_a = 2.f - alpha;

    // write 40 permuted words. logical half i: i<35 mean[i]; 35..69 var[i-35]; else 0
#pragma unroll
    for (int W = 0; W < 40; W++) {
        float lo, hi;
        {
            int i = 2 * W;
            if (i < 35)      { lo = sum[i] * invd; }
            else if (i < 70) { float m = sum[i-35]*invd; lo = sq[i-35]*invd - two_m_a*m*m; }
            else             { lo = 0.f; }
        }
        {
            int i = 2 * W + 1;
            if (i < 35)      { hi = sum[i] * invd; }
            else if (i < 70) { float m = sum[i-35]*invd; hi = sq[i-35]*invd - two_m_a*m*m; }
            else             { hi = 0.f; }
        }
        int kt = W >> 3, q = W & 7;
        int sw = kt * 8 + ((q < 4) ? (2 * q) : (2 * (q - 4) + 1));
        dstrow[sw] = pack_h2(lo, hi);
    }
}

// ---------------------------------------------------------------------------
// Fused persistent kernel: 148 blocks x 384 threads.
// Warps 0-7: register-chain MLP (tile t). Warps 8-11: featurize tile t+148
// into the alternate act buffer. One barrier per tile.
// ---------------------------------------------------------------------------
__global__ void __launch_bounds__(FF_THREADS, 1) fused_kernel(
    const float* __restrict__ xyz,
    const float* __restrict__ b0, const float* __restrict__ b1,
    const float* __restrict__ b2, const float* __restrict__ b3,
    const float* __restrict__ b4,
    const float* __restrict__ w5, const float* __restrict__ b5,
    const float* __restrict__ dw, const float* __restrict__ db,
    float* __restrict__ out) {

    extern __shared__ char smem[];
    uint32_t* actbuf = reinterpret_cast<uint32_t*>(smem);               // 2 tiles
    uint32_t* wsm    = reinterpret_cast<uint32_t*>(smem + 2 * ACT_TILE_BYTES);
    float* bias = reinterpret_cast<float*>(smem + 2 * ACT_TILE_BYTES + WS_ALL_BYTES);
    float* w5s  = bias + 5 * DH;
    float* dws  = w5s + DH * 3;

    const int tid  = threadIdx.x;
    const int lane = tid & 31;
    const int warp = tid >> 5;

    const uint32_t s_w = smem_u32(wsm);

    // stage all 5 weight layers
    for (int i = tid; i < WS_ALL_BYTES / 16; i += FF_THREADS)
        cp16(s_w + (uint32_t)i * 16, g_wpadh + i * 8);
    CP_COMMIT();

    if (tid < DH) {
        bias[0 * DH + tid] = b0[tid];
        bias[1 * DH + tid] = b1[tid];
        bias[2 * DH + tid] = b2[tid];
        bias[3 * DH + tid] = b3[tid];
        bias[4 * DH + tid] = b4[tid];
        dws[tid] = dw[tid];
    }
    for (int i = tid; i < DH * 3; i += FF_THREADS) w5s[i] = w5[i];
    const float db0 = db[0];
    const float b50 = b5[0], b51 = b5[1], b52 = b5[2];

    // warm-up: featurize first tile into buf0 (threads 0..127, 1 pt each)
    if (tid < TM)
        featurize_point(blockIdx.x * TM + tid, xyz, actbuf + tid * ACT_W32);
    CP_WAIT0();
    __syncthreads();

    float acc[16][4];
    uint32_t h[32];

    int it = 0;
    for (int tile = blockIdx.x; tile < NT; tile += FF_GRID, it++) {
        const int p = it & 1;

        if (warp >= 8) {
            // ---- featurize warps: produce tile t+FF_GRID into buf[1-p] ----
            int nt2 = tile + FF_GRID;
            if (nt2 < NT) {
                int ftid = tid - 256;   // 0..127
                featurize_point(nt2 * TM + ftid, xyz,
                                actbuf + (1 - p) * (ACT_TILE_BYTES / 4) + ftid * ACT_W32);
            }
        } else {
            // ---- MLP warps: 5-layer register chain on buf[p] ----
            const uint32_t* actin = actbuf + p * (ACT_TILE_BYTES / 4);
            const int r  = lane >> 2;
            const int cp = lane & 3;
            const int R0 = warp * 16 + r;
            const int R1 = R0 + 8;

            // layer 0 (K=80 -> 5 ksteps), LDS.64 pairs
#pragma unroll
            for (int j = 0; j < 16; j++)
#pragma unroll
                for (int d = 0; d < 4; d++) acc[j][d] = 0.f;
#pragma unroll
            for (int kt = 0; kt < 5; kt++) {
                uint32_t a[4];
                {
                    uint2 u0 = *reinterpret_cast<const uint2*>(
                        &actin[R0 * ACT_W32 + kt * 8 + cp * 2]);
                    uint2 u1 = *reinterpret_cast<const uint2*>(
                        &actin[R1 * ACT_W32 + kt * 8 + cp * 2]);
                    a[0] = u0.x; a[2] = u0.y;
                    a[1] = u1.x; a[3] = u1.y;
                }
#pragma unroll
                for (int j = 0; j < 16; j++) {
                    uint2 bu = *reinterpret_cast<const uint2*>(
                        &wsm[(j * 8 + r) * WS_W32 + kt * 8 + cp * 2]);
                    uint32_t bfr[2] = {bu.x, bu.y};
                    mma_f16(acc[j], a, bfr);
                }
            }

            // pf: bias, sigma head, convert to h
            {
                float sp0 = 0.f, sp1 = 0.f;
#pragma unroll
                for (int j = 0; j < 16; j++) {
                    int c0 = j * 8 + cp * 2;
                    float bv0 = bias[c0], bv1 = bias[c0 + 1];
                    float v0 = acc[j][0] + bv0, v1 = acc[j][1] + bv1;
                    float v2 = acc[j][2] + bv0, v3 = acc[j][3] + bv1;
                    float d0 = dws[c0], d1 = dws[c0 + 1];
                    sp0 = fmaf(v0, d0, fmaf(v1, d1, sp0));
                    sp1 = fmaf(v2, d0, fmaf(v3, d1, sp1));
                    h[j]      = pack_h2(v0, v1);
                    h[16 + j] = pack_h2(v2, v3);
                }
                sp0 += __shfl_xor_sync(0xffffffff, sp0, 1);
                sp0 += __shfl_xor_sync(0xffffffff, sp0, 2);
                sp1 += __shfl_xor_sync(0xffffffff, sp1, 1);
                sp1 += __shfl_xor_sync(0xffffffff, sp1, 2);
                if (cp == 0) {
                    size_t pp = (size_t)tile * TM;
                    out[(pp + R0) * 4 + 3] = fmaxf(sp0 + db0, 0.f);
                    out[(pp + R1) * 4 + 3] = fmaxf(sp1 + db0, 0.f);
                }
            }

            // layers 1..4
#pragma unroll 1
            for (int l = 1; l < 5; l++) {
                const uint32_t* wp = wsm + l * WL_W32;
                const float* bl = bias + l * DH;
#pragma unroll
                for (int j = 0; j < 16; j++)
#pragma unroll
                    for (int d = 0; d < 4; d++) acc[j][d] = 0.f;
#pragma unroll
                for (int kt = 0; kt < 8; kt++) {
                    uint32_t a[4];
                    a[0] = h[2 * kt];
                    a[1] = h[16 + 2 * kt];
                    a[2] = h[2 * kt + 1];
                    a[3] = h[16 + 2 * kt + 1];
#pragma unroll
                    for (int j = 0; j < 16; j++) {
                        uint2 bu = *reinterpret_cast<const uint2*>(
                            &wp[(j * 8 + r) * WS_W32 + kt * 8 + cp * 2]);
                        uint32_t bfr[2] = {bu.x, bu.y};
                        mma_f16(acc[j], a, bfr);
                    }
                }
                if (l < 4) {
#pragma unroll
                    for (int j = 0; j < 16; j++) {
                        int c0 = j * 8 + cp * 2;
                        float bv0 = bl[c0], bv1 = bl[c0 + 1];
                        float v0 = acc[j][0] + bv0, v1 = acc[j][1] + bv1;
                        float v2 = acc[j][2] + bv0, v3 = acc[j][3] + bv1;
                        v0 = v0 > 0.f ? v0 : 0.01f * v0;
                        v1 = v1 > 0.f ? v1 : 0.01f * v1;
                        v2 = v2 > 0.f ? v2 : 0.01f * v2;
                        v3 = v3 > 0.f ? v3 : 0.01f * v3;
                        h[j]      = pack_h2(v0, v1);
                        h[16 + j] = pack_h2(v2, v3);
                    }
                } else {
                    float ra0 = 0.f, ra1 = 0.f, ra2 = 0.f;
                    float rb0 = 0.f, rb1 = 0.f, rb2 = 0.f;
#pragma unroll
                    for (int j = 0; j < 16; j++) {
                        int c0 = j * 8 + cp * 2;
                        float bv0 = bl[c0], bv1 = bl[c0 + 1];
                        float v0 = acc[j][0] + bv0, v1 = acc[j][1] + bv1;
                        float v2 = acc[j][2] + bv0, v3 = acc[j][3] + bv1;
                        v0 = v0 > 0.f ? v0 : 0.01f * v0;
                        v1 = v1 > 0.f ? v1 : 0.01f * v1;
                        v2 = v2 > 0.f ? v2 : 0.01f * v2;
                        v3 = v3 > 0.f ? v3 : 0.01f * v3;
                        float w00 = w5s[c0 * 3 + 0], w01 = w5s[c0 * 3 + 1], w02 = w5s[c0 * 3 + 2];
                        float w10 = w5s[(c0 + 1) * 3 + 0], w11 = w5s[(c0 + 1) * 3 + 1], w12 = w5s[(c0 + 1) * 3 + 2];
                        ra0 = fmaf(v0, w00, fmaf(v1, w10, ra0));
                        ra1 = fmaf(v0, w01, fmaf(v1, w11, ra1));
                        ra2 = fmaf(v0, w02, fmaf(v1, w12, ra2));
                        rb0 = fmaf(v2, w00, fmaf(v3, w10, rb0));
                        rb1 = fmaf(v2, w01, fmaf(v3, w11, rb1));
                        rb2 = fmaf(v2, w02, fmaf(v3, w12, rb2));
                    }
                    ra0 += __shfl_xor_sync(0xffffffff, ra0, 1);
                    ra0 += __shfl_xor_sync(0xffffffff, ra0, 2);
                    ra1 += __shfl_xor_sync(0xffffffff, ra1, 1);
                    ra1 += __shfl_xor_sync(0xffffffff, ra1, 2);
                    ra2 += __shfl_xor_sync(0xffffffff, ra2, 1);
                    ra2 += __shfl_xor_sync(0xffffffff, ra2, 2);
                    rb0 += __shfl_xor_sync(0xffffffff, rb0, 1);
                    rb0 += __shfl_xor_sync(0xffffffff, rb0, 2);
                    rb1 += __shfl_xor_sync(0xffffffff, rb1, 1);
                    rb1 += __shfl_xor_sync(0xffffffff, rb1, 2);
                    rb2 += __shfl_xor_sync(0xffffffff, rb2, 1);
                    rb2 += __shfl_xor_sync(0xffffffff, rb2, 2);
                    if (cp == 0) {
                        size_t pp = (size_t)tile * TM;
                        size_t o0 = (pp + R0) * 4, o1 = (pp + R1) * 4;
                        out[o0 + 0] = tanhf(ra0 + b50);
                        out[o0 + 1] = tanhf(ra1 + b51);
                        out[o0 + 2] = tanhf(ra2 + b52);
                        out[o1 + 0] = tanhf(rb0 + b50);
                        out[o1 + 1] = tanhf(rb1 + b51);
                        out[o1 + 2] = tanhf(rb2 + b52);
                    }
                }
            }
        }
        __syncthreads();   // buf[1-p] complete; buf[p] fully consumed
    }
}

// ---------------------------------------------------------------------------
// Launch
// ---------------------------------------------------------------------------
extern "C" void kernel_launch(void* const* d_in, const int* in_sizes, int n_in,
                              void* d_out, int out_size) {
    const float* xyz       = (const float*)d_in[0];
    const float* src_imgs  = (const float*)d_in[2];
    const float* src_cams  = (const float*)d_in[3];
    const float* src_feats = (const float*)d_in[4];
    const float* w0 = (const float*)d_in[5];
    const float* b0 = (const float*)d_in[6];
    const float* w1 = (const float*)d_in[7];
    const float* b1 = (const float*)d_in[8];
    const float* w2 = (const float*)d_in[9];
    const float* b2 = (const float*)d_in[10];
    const float* w3 = (const float*)d_in[11];
    const float* b3 = (const float*)d_in[12];
    const float* w4 = (const float*)d_in[13];
    const float* b4 = (const float*)d_in[14];
    const float* w5 = (const float*)d_in[15];
    const float* b5 = (const float*)d_in[16];
    const float* dw = (const float*)d_in[17];
    const float* db = (const float*)d_in[18];
    float* out = (float*)d_out;

    const int smem_bytes = 2 * ACT_TILE_BYTES + WS_ALL_BYTES
                         + (5 * DH + DH * 3 + DH) * (int)sizeof(float);
    cudaFuncSetAttribute(fused_kernel,
                         cudaFuncAttributeMaxDynamicSharedMemorySize, smem_bytes);

    proj_kernel<<<1, 32>>>(src_cams);
    wprep_kernel<<<(5 * 128 * WS_W + 255) / 256, 256>>>(w0, w1, w2, w3, w4);
    tfeat_kernel<<<(B_ * NV * H1_ * W1_ * D_) / 256, 256>>>(src_feats);
    timg_kernel<<<(B_ * NV * H_ * W_ * 3 + 255) / 256, 256>>>(src_imgs);
    fused_kernel<<<FF_GRID, FF_THREADS, smem_bytes>>>(xyz, b0, b1, b2, b3, b4,
                                                      w5, b5, dw, db, out);
}